// round 15
// baseline (speedup 1.0000x reference)
#include <cuda_runtime.h>
#include <cuda_bf16.h>
#include <cuda_fp16.h>
#include <cstdint>

// ---------------------------------------------------------------------------
// FeatherNet, all GEMMs 1-pass fp16 HMMA with fp32 accumulate.
//   V   = V1h @ V2h^T        (x64-scaled operands, 2^-12 descale, fp16 out)
//   h   = relu(xh @ W1h^T + b1)   (fp16 out)
//   out = hh @ W2h^T + b2         (fp32 out)
// R15: CTA tile 128x256, warp tile 64x64 (2x4 warp grid). LDSM bytes/MAC
// drop 33% vs 64x32 warps (smem port is the measured bottleneck), barrier
// frequency per MAC halves, global operand traffic halves.
// Mainloop: R5/R11-proven shape — 4-stage cp.async ring (18.4KB/stage),
// K-chunk 16, wait_group 2, LDSM then MMA, issue at end. Occupancy 1.
// ---------------------------------------------------------------------------

using u16 = uint16_t;

#define D_IN   2048
#define D_FF   8192
#define D_OUT  2048
#define BATCH  4096
#define SZN    5794
#define SZM    2897
#define SZN_PAD 5888            // 46*128 = 23*256
#define SZK_PAD 2944            // 184*16

#define OFF_B1 (D_FF * D_IN)                // 16777216
#define OFF_W2 (OFF_B1 + D_FF)              // 16785408
#define OFF_B2 (OFF_W2 + D_OUT * D_FF)      // 33562624

#define V_SCALE     64.0f
#define V_DESCALE   (1.0f / 4096.0f)

// ---------------- device scratch -------------------------------------------
__device__ __half g_V1hi[(size_t)SZN_PAD * SZK_PAD];
__device__ __half g_V2hi[(size_t)SZN_PAD * SZK_PAD];
__device__ __half g_Vh [(size_t)SZN * SZN];          // fp16 V (weights)
__device__ __half g_xh [(size_t)BATCH * D_IN];
__device__ __half g_hh [(size_t)BATCH * D_FF];
__device__ float  g_bias[D_FF + D_OUT];              // [b1 | b2]

// ---------------- PTX helpers ----------------------------------------------
__device__ __forceinline__ uint32_t smem_u32(const void* p) {
    uint32_t a;
    asm("{ .reg .u64 t; cvta.to.shared.u64 t, %1; cvt.u32.u64 %0, t; }"
        : "=r"(a) : "l"(p));
    return a;
}

#define CP16(sm, gp) \
    asm volatile("cp.async.cg.shared.global [%0], [%1], 16;" :: "r"(sm), "l"(gp))
#define CPCOMMIT() asm volatile("cp.async.commit_group;" ::: "memory")
#define CPWAIT2()  asm volatile("cp.async.wait_group 2;" ::: "memory")

#define LDSM4(r0, r1, r2, r3, addr) \
    asm volatile("ldmatrix.sync.aligned.m8n8.x4.shared.b16 {%0,%1,%2,%3}, [%4];" \
                 : "=r"(r0), "=r"(r1), "=r"(r2), "=r"(r3) : "r"(addr))

__device__ __forceinline__ void mma_f16(float* d, const uint32_t* a,
                                        uint32_t b0, uint32_t b1) {
    asm volatile("mma.sync.aligned.m16n8k16.row.col.f32.f16.f16.f32 "
                 "{%0,%1,%2,%3}, {%4,%5,%6,%7}, {%8,%9}, {%0,%1,%2,%3};"
                 : "+f"(d[0]), "+f"(d[1]), "+f"(d[2]), "+f"(d[3])
                 : "r"(a[0]), "r"(a[1]), "r"(a[2]), "r"(a[3]), "r"(b0), "r"(b1));
}

// ---------------- tiling ---------------------------------------------------
// CTA tile 128(M) x 256(N), K-chunk 16. Warp grid 2x4, warp tile 64x64.
#define ROWB      48
#define A_PLANE   (128 * ROWB)          // 6144 B
#define B_PLANE   (256 * ROWB)          // 12288 B
#define NSTAGE    4
#define STG       ((uint32_t)(A_PLANE + B_PLANE))    // 18432 B
#define OA_HI     0u
#define OB_HI     ((uint32_t)A_PLANE)
#define SMEM_1P   (NSTAGE * (A_PLANE + B_PLANE))     // 73728 B

// ---------------------------------------------------------------------------
// fp32 -> scaled fp16 plane [prows, pcols], zero pad.
// ---------------------------------------------------------------------------
__global__ void tohalf_pad(const float* __restrict__ src, __half* __restrict__ hi,
                           int rows, int cols, int prows, int pcols, float scale)
{
    int idx = blockIdx.x * blockDim.x + threadIdx.x;
    int total = prows * pcols;
    if (idx >= total) return;
    int r = idx / pcols;
    int c = idx - r * pcols;
    float v = (r < rows && c < cols) ? src[(size_t)r * cols + c] * scale : 0.0f;
    hi[idx] = __float2half_rn(v);
}

__global__ void tohalf(const float* __restrict__ src, __half* __restrict__ hi, int n)
{
    int i = blockIdx.x * blockDim.x + threadIdx.x;
    if (i >= n) return;
    hi[i] = __float2half_rn(src[i]);
}

// ---------------------------------------------------------------------------
// bias: out[j] = dot(V1[r,:], V2[c,:]) fp32, warp per output.
// ---------------------------------------------------------------------------
__global__ void bias_kernel(const float* __restrict__ V1, const float* __restrict__ V2,
                            float* __restrict__ biases)
{
    int w = (blockIdx.x * blockDim.x + threadIdx.x) >> 5;
    int lane = threadIdx.x & 31;
    if (w >= D_FF + D_OUT) return;
    size_t flat = (w < D_FF) ? ((size_t)OFF_B1 + w) : ((size_t)OFF_B2 + (w - D_FF));
    int r = (int)(flat / SZN);
    int c = (int)(flat - (size_t)r * SZN);
    const float* a = V1 + (size_t)r * SZM;
    const float* b = V2 + (size_t)c * SZM;
    float s = 0.0f;
    for (int k = lane; k < SZM; k += 32)
        s = fmaf(__ldg(a + k), __ldg(b + k), s);
    #pragma unroll
    for (int o = 16; o > 0; o >>= 1)
        s += __shfl_xor_sync(0xFFFFFFFFu, s, o);
    if (lane == 0) biases[w] = s;
}

// ---------------------------------------------------------------------------
// fp16 1-pass GEMM (tile 128x256): C = oscale * (A @ B^T) (+bias) (relu)
// EMIT: 0 = fp32 C | 1 = fp16 Ch
// ---------------------------------------------------------------------------
template<bool BIAS, bool RELU, int EMIT, bool BOUND>
__global__ __launch_bounds__(256, 1)
void gemm_mma(const u16* __restrict__ Ahi, const u16* __restrict__ Bhi,
              const float* __restrict__ bias,
              float* __restrict__ C, __half* __restrict__ Ch,
              int M, int N, int K, int lda, int ldb, int ldc, float oscale)
{
    extern __shared__ char smem[];
    const uint32_t sb = smem_u32(smem);
    const int tid  = threadIdx.x;
    const int lane = tid & 31, wid = tid >> 5;
    const int wm = wid >> 2;        // 0..1 : 64 rows
    const int wn = wid & 3;         // 0..3 : 64 cols
    const int brow = blockIdx.y * 128;
    const int bcol = blockIdx.x * 256;

    // cp.async geometry: A 1 CP16/thread, B 2 CP16/thread
    const int lrow = tid >> 1, lch = tid & 1;
    const u16* gAh = Ahi + (size_t)(brow + lrow) * lda + lch * 8;
    const u16* gB0 = Bhi + (size_t)(bcol + lrow) * ldb + lch * 8;
    const u16* gB1 = Bhi + (size_t)(bcol + 128 + lrow) * ldb + lch * 8;
    const uint32_t stByte  = (uint32_t)(lrow * ROWB + lch * 16);
    const uint32_t stByteB1 = stByte + 128 * ROWB;

    const uint32_t aByte = (uint32_t)((wm * 64 + (lane & 15)) * ROWB + (lane >> 4) * 16);
    const uint32_t bByte = (uint32_t)((wn * 64 + (lane & 15)) * ROWB + (lane >> 4) * 16);

    float acc[4][8][4];
    #pragma unroll
    for (int t = 0; t < 4; ++t)
        #pragma unroll
        for (int u = 0; u < 8; ++u)
            #pragma unroll
            for (int e = 0; e < 4; ++e) acc[t][u][e] = 0.0f;

    const int nk = K >> 4;

    auto issue = [&](int kb) {
        const uint32_t st = sb + (uint32_t)(kb & (NSTAGE - 1)) * STG;
        const size_t go = (size_t)kb * 16;
        CP16(st + OA_HI + stByte,   gAh + go);
        CP16(st + OB_HI + stByte,   gB0 + go);
        CP16(st + OB_HI + stByteB1, gB1 + go);
        CPCOMMIT();
    };

    issue(0); issue(1); issue(2);

    #pragma unroll 1
    for (int i = 0; i < nk; ++i) {
        CPWAIT2();
        __syncthreads();
        const uint32_t st = sb + (uint32_t)(i & (NSTAGE - 1)) * STG;

        uint32_t ah[16], bh[16];
        LDSM4(bh[0],  bh[1],  bh[2],  bh[3],  st + OB_HI + bByte);
        LDSM4(bh[4],  bh[5],  bh[6],  bh[7],  st + OB_HI + bByte + 16 * ROWB);
        LDSM4(bh[8],  bh[9],  bh[10], bh[11], st + OB_HI + bByte + 32 * ROWB);
        LDSM4(bh[12], bh[13], bh[14], bh[15], st + OB_HI + bByte + 48 * ROWB);
        LDSM4(ah[0],  ah[1],  ah[2],  ah[3],  st + OA_HI + aByte);
        LDSM4(ah[4],  ah[5],  ah[6],  ah[7],  st + OA_HI + aByte + 16 * ROWB);
        LDSM4(ah[8],  ah[9],  ah[10], ah[11], st + OA_HI + aByte + 32 * ROWB);
        LDSM4(ah[12], ah[13], ah[14], ah[15], st + OA_HI + aByte + 48 * ROWB);

        #pragma unroll
        for (int t = 0; t < 4; ++t)
            #pragma unroll
            for (int u = 0; u < 8; ++u) {
                const int g = u >> 1, q = u & 1;
                mma_f16(acc[t][u], &ah[4*t], bh[4*g + q], bh[4*g + q + 2]);
            }

        if (i + 3 < nk) issue(i + 3);   // issue-at-end (R5-proven placement)
    }

    // ---------------- epilogue (registers -> global, direct) ----------------
    const int l4  = lane >> 2;
    const int lc2 = (lane & 3) * 2;
    #pragma unroll
    for (int u = 0; u < 8; ++u) {
        const int col = bcol + wn * 64 + u * 8 + lc2;
        float b0 = 0.0f, b1 = 0.0f;
        if (BIAS) {
            b0 = __ldg(bias + col);
            b1 = __ldg(bias + col + 1);
        }
        #pragma unroll
        for (int t = 0; t < 4; ++t)
            #pragma unroll
            for (int h = 0; h < 2; ++h) {
                const int row = brow + wm * 64 + t * 16 + h * 8 + l4;
                // N even & col even -> pair [col, col+1] inside when col < N
                if (BOUND && (row >= M || col >= N)) continue;
                float v0 = acc[t][u][2*h + 0] * oscale;
                float v1 = acc[t][u][2*h + 1] * oscale;
                if (BIAS) { v0 += b0; v1 += b1; }
                if (RELU) { v0 = fmaxf(v0, 0.0f); v1 = fmaxf(v1, 0.0f); }
                const size_t o = (size_t)row * ldc + col;
                if (EMIT == 0) {
                    float2 f2; f2.x = v0; f2.y = v1;
                    *(float2*)(C + o) = f2;
                } else {
                    *(__half2*)(Ch + o) = __floats2half2_rn(v0, v1);
                }
            }
    }
}

// ---------------------------------------------------------------------------
// kernel_launch
// ---------------------------------------------------------------------------
extern "C" void kernel_launch(void* const* d_in, const int* in_sizes, int n_in,
                              void* d_out, int out_size)
{
    const float* x  = (const float*)d_in[0];   // [4096, 2048]
    const float* V1 = (const float*)d_in[1];   // [5794, 2897]
    const float* V2 = (const float*)d_in[2];   // [5794, 2897]
    float* out = (float*)d_out;                // [4096, 2048]

    __half *v1h, *v2h, *vh, *xh, *hh;
    float* gb;
    cudaGetSymbolAddress((void**)&v1h, g_V1hi);
    cudaGetSymbolAddress((void**)&v2h, g_V2hi);
    cudaGetSymbolAddress((void**)&vh,  g_Vh);
    cudaGetSymbolAddress((void**)&xh,  g_xh);
    cudaGetSymbolAddress((void**)&hh,  g_hh);
    cudaGetSymbolAddress((void**)&gb,  g_bias);

    auto k1 = gemm_mma<false, false, 1, true>;   // V  (fp16 out, bounded)
    auto k2 = gemm_mma<true,  true,  1, false>;  // h  (fp16 out)
    auto k3 = gemm_mma<true,  false, 0, false>;  // out (fp32)
    cudaFuncSetAttribute(k1, cudaFuncAttributeMaxDynamicSharedMemorySize, SMEM_1P);
    cudaFuncSetAttribute(k2, cudaFuncAttributeMaxDynamicSharedMemorySize, SMEM_1P);
    cudaFuncSetAttribute(k3, cudaFuncAttributeMaxDynamicSharedMemorySize, SMEM_1P);

    // 1. operand prep
    {
        int total = SZN_PAD * SZK_PAD;
        tohalf_pad<<<(total + 255) / 256, 256>>>(
            V1, v1h, SZN, SZM, SZN_PAD, SZK_PAD, V_SCALE);
        tohalf_pad<<<(total + 255) / 256, 256>>>(
            V2, v2h, SZN, SZM, SZN_PAD, SZK_PAD, V_SCALE);
        int totx = BATCH * D_IN;
        tohalf<<<(totx + 255) / 256, 256>>>(x, xh, totx);
        bias_kernel<<<(D_FF + D_OUT) / 8, 256>>>(V1, V2, gb);
    }

    // 2. V = V1h @ V2h^T  (x4096 scaled) -> fp16 Vh (descale 2^-12)
    k1<<<dim3(SZN_PAD / 256, SZN_PAD / 128), 256, SMEM_1P>>>(
        (const u16*)v1h, (const u16*)v2h,
        nullptr, nullptr, vh,
        SZN, SZN, SZK_PAD, SZK_PAD, SZK_PAD, SZN, V_DESCALE);

    // 3. h = relu(xh @ W1h^T + b1) -> fp16
    k2<<<dim3(D_FF / 256, BATCH / 128), 256, SMEM_1P>>>(
        (const u16*)xh, (const u16*)vh,
        gb, nullptr, hh,
        BATCH, D_FF, D_IN, D_IN, D_IN, D_FF, 1.0f);

    // 4. out = hh @ W2h^T + b2 -> fp32
    k3<<<dim3(D_OUT / 256, BATCH / 128), 256, SMEM_1P>>>(
        (const u16*)hh, (const u16*)(vh + OFF_W2),
        gb + D_FF, out, nullptr,
        BATCH, D_OUT, D_FF, D_FF, D_FF, D_OUT, 1.0f);
}

// round 16
// speedup vs baseline: 1.5438x; 1.5438x over previous
#include <cuda_runtime.h>
#include <cuda_bf16.h>
#include <cuda_fp16.h>
#include <cstdint>

// ---------------------------------------------------------------------------
// FeatherNet, all GEMMs 1-pass fp16 HMMA with fp32 accumulate.
//   V   = V1h @ V2h^T        (x64-scaled operands, 2^-12 descale, fp16 out)
//   h   = relu(xh @ W1h^T + b1)   (fp16 out)
//   out = hh @ W2h^T + b2         (fp32 out)
// R16: exact R11 kernel (best: 1770us) with ONE change — two K-chunks per
// __syncthreads (wait_group 2 guarantees both stages ready), NSTAGE 5->6 for
// overwrite safety. Same registers, same LDSM->MMA order, same epilogue.
// ---------------------------------------------------------------------------

using u16 = uint16_t;

#define D_IN   2048
#define D_FF   8192
#define D_OUT  2048
#define BATCH  4096
#define SZN    5794
#define SZM    2897
#define SZN_PAD 5888            // 46*128
#define SZK_PAD 2944            // 184*16 (nk even for all GEMMs)

#define OFF_B1 (D_FF * D_IN)                // 16777216
#define OFF_W2 (OFF_B1 + D_FF)              // 16785408
#define OFF_B2 (OFF_W2 + D_OUT * D_FF)      // 33562624

#define V_SCALE     64.0f
#define V_DESCALE   (1.0f / 4096.0f)

// ---------------- device scratch -------------------------------------------
__device__ __half g_V1hi[(size_t)SZN_PAD * SZK_PAD];
__device__ __half g_V2hi[(size_t)SZN_PAD * SZK_PAD];
__device__ __half g_Vh [(size_t)SZN * SZN];          // fp16 V (weights)
__device__ __half g_xh [(size_t)BATCH * D_IN];
__device__ __half g_hh [(size_t)BATCH * D_FF];
__device__ float  g_bias[D_FF + D_OUT];              // [b1 | b2]

// ---------------- PTX helpers ----------------------------------------------
__device__ __forceinline__ uint32_t smem_u32(const void* p) {
    uint32_t a;
    asm("{ .reg .u64 t; cvta.to.shared.u64 t, %1; cvt.u32.u64 %0, t; }"
        : "=r"(a) : "l"(p));
    return a;
}

#define CP16(sm, gp) \
    asm volatile("cp.async.cg.shared.global [%0], [%1], 16;" :: "r"(sm), "l"(gp))
#define CPCOMMIT() asm volatile("cp.async.commit_group;" ::: "memory")
#define CPWAIT2()  asm volatile("cp.async.wait_group 2;" ::: "memory")

#define LDSM4(r0, r1, r2, r3, addr) \
    asm volatile("ldmatrix.sync.aligned.m8n8.x4.shared.b16 {%0,%1,%2,%3}, [%4];" \
                 : "=r"(r0), "=r"(r1), "=r"(r2), "=r"(r3) : "r"(addr))

__device__ __forceinline__ void mma_f16(float* d, const uint32_t* a,
                                        uint32_t b0, uint32_t b1) {
    asm volatile("mma.sync.aligned.m16n8k16.row.col.f32.f16.f16.f32 "
                 "{%0,%1,%2,%3}, {%4,%5,%6,%7}, {%8,%9}, {%0,%1,%2,%3};"
                 : "+f"(d[0]), "+f"(d[1]), "+f"(d[2]), "+f"(d[3])
                 : "r"(a[0]), "r"(a[1]), "r"(a[2]), "r"(a[3]), "r"(b0), "r"(b1));
}

// ---------------- tiling ---------------------------------------------------
#define ROWB      48
#define PLANE     (128 * ROWB)          // 6144 B
#define NSTAGE    6
#define STG       (2 * PLANE)           // 12288 B per stage (A_HI, B_HI)
#define OA_HI     0u
#define OB_HI     ((uint32_t)PLANE)
#define SMEM_1P   (NSTAGE * STG)        // 73728 B

// ---------------------------------------------------------------------------
// fp32 -> scaled fp16 plane [prows, pcols], zero pad.
// ---------------------------------------------------------------------------
__global__ void tohalf_pad(const float* __restrict__ src, __half* __restrict__ hi,
                           int rows, int cols, int prows, int pcols, float scale)
{
    int idx = blockIdx.x * blockDim.x + threadIdx.x;
    int total = prows * pcols;
    if (idx >= total) return;
    int r = idx / pcols;
    int c = idx - r * pcols;
    float v = (r < rows && c < cols) ? src[(size_t)r * cols + c] * scale : 0.0f;
    hi[idx] = __float2half_rn(v);
}

__global__ void tohalf(const float* __restrict__ src, __half* __restrict__ hi, int n)
{
    int i = blockIdx.x * blockDim.x + threadIdx.x;
    if (i >= n) return;
    hi[i] = __float2half_rn(src[i]);
}

// ---------------------------------------------------------------------------
// bias: out[j] = dot(V1[r,:], V2[c,:]) fp32, warp per output.
// ---------------------------------------------------------------------------
__global__ void bias_kernel(const float* __restrict__ V1, const float* __restrict__ V2,
                            float* __restrict__ biases)
{
    int w = (blockIdx.x * blockDim.x + threadIdx.x) >> 5;
    int lane = threadIdx.x & 31;
    if (w >= D_FF + D_OUT) return;
    size_t flat = (w < D_FF) ? ((size_t)OFF_B1 + w) : ((size_t)OFF_B2 + (w - D_FF));
    int r = (int)(flat / SZN);
    int c = (int)(flat - (size_t)r * SZN);
    const float* a = V1 + (size_t)r * SZM;
    const float* b = V2 + (size_t)c * SZM;
    float s = 0.0f;
    for (int k = lane; k < SZM; k += 32)
        s = fmaf(__ldg(a + k), __ldg(b + k), s);
    #pragma unroll
    for (int o = 16; o > 0; o >>= 1)
        s += __shfl_xor_sync(0xFFFFFFFFu, s, o);
    if (lane == 0) biases[w] = s;
}

// ---------------------------------------------------------------------------
// fp16 1-pass GEMM: C[M,N] = oscale * (A @ B^T) (+bias) (relu)
// EMIT: 0 = fp32 C | 1 = fp16 Ch
// ---------------------------------------------------------------------------
template<bool BIAS, bool RELU, int EMIT, bool BOUND>
__global__ __launch_bounds__(256, 1)
void gemm_mma(const u16* __restrict__ Ahi, const u16* __restrict__ Bhi,
              const float* __restrict__ bias,
              float* __restrict__ C, __half* __restrict__ Ch,
              int M, int N, int K, int lda, int ldb, int ldc, float oscale)
{
    extern __shared__ char smem[];
    const uint32_t sb = smem_u32(smem);
    const int tid  = threadIdx.x;
    const int lane = tid & 31, wid = tid >> 5;
    const int wm = wid >> 2;        // 0..1 : 64 rows
    const int wn = wid & 3;         // 0..3 : 32 cols
    const int brow = blockIdx.y * 128;
    const int bcol = blockIdx.x * 128;

    // cp.async geometry: thread -> (row, 16B chunk)
    const int lrow = tid >> 1, lch = tid & 1;
    const u16* gAh = Ahi + (size_t)(brow + lrow) * lda + lch * 8;
    const u16* gBh = Bhi + (size_t)(bcol + lrow) * ldb + lch * 8;
    const uint32_t stByte = (uint32_t)(lrow * ROWB + lch * 16);

    const uint32_t aByte = (uint32_t)((wm * 64 + (lane & 15)) * ROWB + (lane >> 4) * 16);
    const uint32_t bByte = (uint32_t)((wn * 32 + (lane & 15)) * ROWB + (lane >> 4) * 16);

    float acc[4][4][4];
    #pragma unroll
    for (int t = 0; t < 4; ++t)
        #pragma unroll
        for (int u = 0; u < 4; ++u)
            #pragma unroll
            for (int e = 0; e < 4; ++e) acc[t][u][e] = 0.0f;

    const int nk = K >> 4;          // even for all our K

    auto issue = [&](int kb) {
        const uint32_t st = sb + (uint32_t)(kb % NSTAGE) * STG + stByte;
        const size_t go = (size_t)kb * 16;
        CP16(st + OA_HI, gAh + go);
        CP16(st + OB_HI, gBh + go);
        CPCOMMIT();
    };

    // single fragment buffer, reused sequentially (compile-time indices)
    uint32_t ah[16], bh[8];

#define LDSM_STAGE(stg) do {                                                   \
    const uint32_t _st = sb + (uint32_t)(stg) * STG;                           \
    LDSM4(bh[0], bh[1], bh[2], bh[3], _st + OB_HI + bByte);                    \
    LDSM4(bh[4], bh[5], bh[6], bh[7], _st + OB_HI + bByte + 16 * ROWB);        \
    LDSM4(ah[0],  ah[1],  ah[2],  ah[3],  _st + OA_HI + aByte);                \
    LDSM4(ah[4],  ah[5],  ah[6],  ah[7],  _st + OA_HI + aByte + 16 * ROWB);    \
    LDSM4(ah[8],  ah[9],  ah[10], ah[11], _st + OA_HI + aByte + 32 * ROWB);    \
    LDSM4(ah[12], ah[13], ah[14], ah[15], _st + OA_HI + aByte + 48 * ROWB);    \
} while (0)

#define MMA_ALL() do {                                                         \
    _Pragma("unroll")                                                          \
    for (int t = 0; t < 4; ++t) {                                              \
        _Pragma("unroll")                                                      \
        for (int u = 0; u < 4; ++u) {                                          \
            const int p = u >> 1, q = u & 1;                                   \
            mma_f16(acc[t][u], &ah[4*t], bh[4*p + q], bh[4*p + q + 2]);        \
        }                                                                      \
    }                                                                          \
} while (0)

    issue(0); issue(1); issue(2); issue(3);

    #pragma unroll 1
    for (int i = 0; i < nk; i += 2) {
        CPWAIT2();                 // <=2 groups outstanding -> stages i, i+1 done
        __syncthreads();           // also: all warps finished reading i-2, i-1

        LDSM_STAGE(i % NSTAGE);
        MMA_ALL();
        LDSM_STAGE((i + 1) % NSTAGE);
        MMA_ALL();

        // stage (i+4)%6 = (i-2)%6, stage (i+5)%6 = (i-1)%6: both consumed
        // before this iteration's barrier -> safe to overwrite.
        if (i + 4 < nk) issue(i + 4);
        if (i + 5 < nk) issue(i + 5);
    }

#undef LDSM_STAGE
#undef MMA_ALL

    // ---------------- epilogue (registers -> global, direct) ----------------
    const int l4  = lane >> 2;
    const int lc2 = (lane & 3) * 2;
    #pragma unroll
    for (int u = 0; u < 4; ++u) {
        const int col = bcol + wn * 32 + u * 8 + lc2;
        float b0 = 0.0f, b1 = 0.0f;
        if (BIAS) {
            b0 = __ldg(bias + col);
            b1 = __ldg(bias + col + 1);
        }
        #pragma unroll
        for (int t = 0; t < 4; ++t)
            #pragma unroll
            for (int h = 0; h < 2; ++h) {
                const int row = brow + wm * 64 + t * 16 + h * 8 + l4;
                // N even & col even -> pair [col, col+1] inside when col < N
                if (BOUND && (row >= M || col >= N)) continue;
                float v0 = acc[t][u][2*h + 0] * oscale;
                float v1 = acc[t][u][2*h + 1] * oscale;
                if (BIAS) { v0 += b0; v1 += b1; }
                if (RELU) { v0 = fmaxf(v0, 0.0f); v1 = fmaxf(v1, 0.0f); }
                const size_t o = (size_t)row * ldc + col;
                if (EMIT == 0) {
                    float2 f2; f2.x = v0; f2.y = v1;
                    *(float2*)(C + o) = f2;
                } else {
                    *(__half2*)(Ch + o) = __floats2half2_rn(v0, v1);
                }
            }
    }
}

// ---------------------------------------------------------------------------
// kernel_launch
// ---------------------------------------------------------------------------
extern "C" void kernel_launch(void* const* d_in, const int* in_sizes, int n_in,
                              void* d_out, int out_size)
{
    const float* x  = (const float*)d_in[0];   // [4096, 2048]
    const float* V1 = (const float*)d_in[1];   // [5794, 2897]
    const float* V2 = (const float*)d_in[2];   // [5794, 2897]
    float* out = (float*)d_out;                // [4096, 2048]

    __half *v1h, *v2h, *vh, *xh, *hh;
    float* gb;
    cudaGetSymbolAddress((void**)&v1h, g_V1hi);
    cudaGetSymbolAddress((void**)&v2h, g_V2hi);
    cudaGetSymbolAddress((void**)&vh,  g_Vh);
    cudaGetSymbolAddress((void**)&xh,  g_xh);
    cudaGetSymbolAddress((void**)&hh,  g_hh);
    cudaGetSymbolAddress((void**)&gb,  g_bias);

    auto k1 = gemm_mma<false, false, 1, true>;   // V  (fp16 out, bounded)
    auto k2 = gemm_mma<true,  true,  1, false>;  // h  (fp16 out)
    auto k3 = gemm_mma<true,  false, 0, false>;  // out (fp32)
    cudaFuncSetAttribute(k1, cudaFuncAttributeMaxDynamicSharedMemorySize, SMEM_1P);
    cudaFuncSetAttribute(k2, cudaFuncAttributeMaxDynamicSharedMemorySize, SMEM_1P);
    cudaFuncSetAttribute(k3, cudaFuncAttributeMaxDynamicSharedMemorySize, SMEM_1P);

    // 1. operand prep
    {
        int total = SZN_PAD * SZK_PAD;
        tohalf_pad<<<(total + 255) / 256, 256>>>(
            V1, v1h, SZN, SZM, SZN_PAD, SZK_PAD, V_SCALE);
        tohalf_pad<<<(total + 255) / 256, 256>>>(
            V2, v2h, SZN, SZM, SZN_PAD, SZK_PAD, V_SCALE);
        int totx = BATCH * D_IN;
        tohalf<<<(totx + 255) / 256, 256>>>(x, xh, totx);
        bias_kernel<<<(D_FF + D_OUT) / 8, 256>>>(V1, V2, gb);
    }

    // 2. V = V1h @ V2h^T  (x4096 scaled) -> fp16 Vh (descale 2^-12)
    k1<<<dim3(SZN_PAD / 128, SZN_PAD / 128), 256, SMEM_1P>>>(
        (const u16*)v1h, (const u16*)v2h,
        nullptr, nullptr, vh,
        SZN, SZN, SZK_PAD, SZK_PAD, SZK_PAD, SZN, V_DESCALE);

    // 3. h = relu(xh @ W1h^T + b1) -> fp16
    k2<<<dim3(D_FF / 128, BATCH / 128), 256, SMEM_1P>>>(
        (const u16*)xh, (const u16*)vh,
        gb, nullptr, hh,
        BATCH, D_FF, D_IN, D_IN, D_IN, D_FF, 1.0f);

    // 4. out = hh @ W2h^T + b2 -> fp32
    k3<<<dim3(D_OUT / 128, BATCH / 128), 256, SMEM_1P>>>(
        (const u16*)hh, (const u16*)(vh + OFF_W2),
        gb + D_FF, out, nullptr,
        BATCH, D_OUT, D_FF, D_FF, D_FF, D_OUT, 1.0f);
}

// round 17
// speedup vs baseline: 1.9694x; 1.2757x over previous
#include <cuda_runtime.h>
#include <cuda_bf16.h>
#include <cuda_fp16.h>
#include <cstdint>

// ---------------------------------------------------------------------------
// FeatherNet, all GEMMs 1-pass fp16 HMMA with fp32 accumulate.
//   V   = V1h @ V2h^T        (x64-scaled operands, 2^-12 descale, fp16 out)
//   h   = relu(xh @ W1h^T + b1)   (fp16 out)
//   out = hh @ W2h^T + b2         (fp32 out)
// R17: GEMM kernel is byte-identical to R11 (best: 1770us; five structural
// variants all lost — it is at its fixed point). Changes limited to operand
// prep: division-free, vectorized pad/split kernels (row-per-block, uint4
// stores, V1+V2 in one launch).
// ---------------------------------------------------------------------------

using u16 = uint16_t;

#define D_IN   2048
#define D_FF   8192
#define D_OUT  2048
#define BATCH  4096
#define SZN    5794
#define SZM    2897
#define SZN_PAD 5888            // 46*128
#define SZK_PAD 2944            // 184*16

#define OFF_B1 (D_FF * D_IN)                // 16777216
#define OFF_W2 (OFF_B1 + D_FF)              // 16785408
#define OFF_B2 (OFF_W2 + D_OUT * D_FF)      // 33562624

#define V_SCALE     64.0f
#define V_DESCALE   (1.0f / 4096.0f)

// ---------------- device scratch -------------------------------------------
__device__ __half g_V1hi[(size_t)SZN_PAD * SZK_PAD];
__device__ __half g_V2hi[(size_t)SZN_PAD * SZK_PAD];
__device__ __half g_Vh [(size_t)SZN * SZN];          // fp16 V (weights)
__device__ __half g_xh [(size_t)BATCH * D_IN];
__device__ __half g_hh [(size_t)BATCH * D_FF];
__device__ float  g_bias[D_FF + D_OUT];              // [b1 | b2]

// ---------------- PTX helpers ----------------------------------------------
__device__ __forceinline__ uint32_t smem_u32(const void* p) {
    uint32_t a;
    asm("{ .reg .u64 t; cvta.to.shared.u64 t, %1; cvt.u32.u64 %0, t; }"
        : "=r"(a) : "l"(p));
    return a;
}

#define CP16(sm, gp) \
    asm volatile("cp.async.cg.shared.global [%0], [%1], 16;" :: "r"(sm), "l"(gp))
#define CPCOMMIT() asm volatile("cp.async.commit_group;" ::: "memory")
#define CPWAIT3()  asm volatile("cp.async.wait_group 3;" ::: "memory")

#define LDSM4(r0, r1, r2, r3, addr) \
    asm volatile("ldmatrix.sync.aligned.m8n8.x4.shared.b16 {%0,%1,%2,%3}, [%4];" \
                 : "=r"(r0), "=r"(r1), "=r"(r2), "=r"(r3) : "r"(addr))

__device__ __forceinline__ void mma_f16(float* d, const uint32_t* a,
                                        uint32_t b0, uint32_t b1) {
    asm volatile("mma.sync.aligned.m16n8k16.row.col.f32.f16.f16.f32 "
                 "{%0,%1,%2,%3}, {%4,%5,%6,%7}, {%8,%9}, {%0,%1,%2,%3};"
                 : "+f"(d[0]), "+f"(d[1]), "+f"(d[2]), "+f"(d[3])
                 : "r"(a[0]), "r"(a[1]), "r"(a[2]), "r"(a[3]), "r"(b0), "r"(b1));
}

// ---------------- tiling ---------------------------------------------------
#define ROWB      48
#define PLANE     (128 * ROWB)          // 6144 B
#define NSTAGE    5
#define STG       (2 * PLANE)           // 12288 B per stage (A_HI, B_HI)
#define OA_HI     0u
#define OB_HI     ((uint32_t)PLANE)
#define SMEM_1P   (NSTAGE * STG)        // 61440 B

// ---------------------------------------------------------------------------
// R17 prep: division-free vectorized pad/split for V1+V2 (one launch).
// Grid: x = row (0..SZN_PAD-1), y = tensor select. Block 384 threads, each
// handling 8 consecutive elements (one 16B uint4 store into the fp16 plane).
// ---------------------------------------------------------------------------
__global__ void pad_split_v(const float* __restrict__ V1, const float* __restrict__ V2,
                            __half* __restrict__ v1h, __half* __restrict__ v2h)
{
    const int row = blockIdx.x;
    const int c8  = threadIdx.x * 8;
    if (c8 >= SZK_PAD) return;
    const float* __restrict__ src = blockIdx.y ? V2 : V1;
    __half*       __restrict__ dst = blockIdx.y ? v2h : v1h;

    __half2 o[4];
    if (row < SZN) {
        const float* s = src + (size_t)row * SZM + c8;
        #pragma unroll
        for (int j = 0; j < 4; ++j) {
            float a = (c8 + 2*j     < SZM) ? s[2*j]     * V_SCALE : 0.0f;
            float b = (c8 + 2*j + 1 < SZM) ? s[2*j + 1] * V_SCALE : 0.0f;
            o[j] = __floats2half2_rn(a, b);
        }
    } else {
        #pragma unroll
        for (int j = 0; j < 4; ++j) o[j] = __floats2half2_rn(0.0f, 0.0f);
    }
    *(uint4*)(dst + (size_t)row * SZK_PAD + c8) = *reinterpret_cast<uint4*>(o);
}

// x -> fp16, vectorized: each thread converts 8 elements (float4 x2 -> uint4).
__global__ void tohalf_vec(const float* __restrict__ src, __half* __restrict__ hi, int n)
{
    int i8 = (blockIdx.x * blockDim.x + threadIdx.x) * 8;
    if (i8 >= n) return;
    float4 a = *(const float4*)(src + i8);
    float4 b = *(const float4*)(src + i8 + 4);
    __half2 o[4];
    o[0] = __floats2half2_rn(a.x, a.y);
    o[1] = __floats2half2_rn(a.z, a.w);
    o[2] = __floats2half2_rn(b.x, b.y);
    o[3] = __floats2half2_rn(b.z, b.w);
    *(uint4*)(hi + i8) = *reinterpret_cast<uint4*>(o);
}

// ---------------------------------------------------------------------------
// bias: out[j] = dot(V1[r,:], V2[c,:]) fp32, warp per output.
// ---------------------------------------------------------------------------
__global__ void bias_kernel(const float* __restrict__ V1, const float* __restrict__ V2,
                            float* __restrict__ biases)
{
    int w = (blockIdx.x * blockDim.x + threadIdx.x) >> 5;
    int lane = threadIdx.x & 31;
    if (w >= D_FF + D_OUT) return;
    size_t flat = (w < D_FF) ? ((size_t)OFF_B1 + w) : ((size_t)OFF_B2 + (w - D_FF));
    int r = (int)(flat / SZN);
    int c = (int)(flat - (size_t)r * SZN);
    const float* a = V1 + (size_t)r * SZM;
    const float* b = V2 + (size_t)c * SZM;
    float s = 0.0f;
    for (int k = lane; k < SZM; k += 32)
        s = fmaf(__ldg(a + k), __ldg(b + k), s);
    #pragma unroll
    for (int o = 16; o > 0; o >>= 1)
        s += __shfl_xor_sync(0xFFFFFFFFu, s, o);
    if (lane == 0) biases[w] = s;
}

// ---------------------------------------------------------------------------
// fp16 1-pass GEMM (byte-identical to R11): C = oscale*(A @ B^T) (+bias)(relu)
// EMIT: 0 = fp32 C | 1 = fp16 Ch
// ---------------------------------------------------------------------------
template<bool BIAS, bool RELU, int EMIT, bool BOUND>
__global__ __launch_bounds__(256, 1)
void gemm_mma(const u16* __restrict__ Ahi, const u16* __restrict__ Bhi,
              const float* __restrict__ bias,
              float* __restrict__ C, __half* __restrict__ Ch,
              int M, int N, int K, int lda, int ldb, int ldc, float oscale)
{
    extern __shared__ char smem[];
    const uint32_t sb = smem_u32(smem);
    const int tid  = threadIdx.x;
    const int lane = tid & 31, wid = tid >> 5;
    const int wm = wid >> 2;        // 0..1 : 64 rows
    const int wn = wid & 3;         // 0..3 : 32 cols
    const int brow = blockIdx.y * 128;
    const int bcol = blockIdx.x * 128;

    // cp.async geometry: thread -> (row, 16B chunk)
    const int lrow = tid >> 1, lch = tid & 1;
    const u16* gAh = Ahi + (size_t)(brow + lrow) * lda + lch * 8;
    const u16* gBh = Bhi + (size_t)(bcol + lrow) * ldb + lch * 8;
    const uint32_t stByte = (uint32_t)(lrow * ROWB + lch * 16);

    const uint32_t aByte = (uint32_t)((wm * 64 + (lane & 15)) * ROWB + (lane >> 4) * 16);
    const uint32_t bByte = (uint32_t)((wn * 32 + (lane & 15)) * ROWB + (lane >> 4) * 16);

    float acc[4][4][4];
    #pragma unroll
    for (int t = 0; t < 4; ++t)
        #pragma unroll
        for (int u = 0; u < 4; ++u)
            #pragma unroll
            for (int e = 0; e < 4; ++e) acc[t][u][e] = 0.0f;

    const int nk = K >> 4;

    auto issue = [&](int kb) {
        const uint32_t st = sb + (uint32_t)(kb % NSTAGE) * STG + stByte;
        const size_t go = (size_t)kb * 16;
        CP16(st + OA_HI, gAh + go);
        CP16(st + OB_HI, gBh + go);
        CPCOMMIT();
    };

    issue(0); issue(1); issue(2); issue(3);

    #pragma unroll 1
    for (int i = 0; i < nk; ++i) {
        CPWAIT3();
        __syncthreads();
        const uint32_t st = sb + (uint32_t)(i % NSTAGE) * STG;

        uint32_t bh[8], ah[16];
        LDSM4(bh[0], bh[1], bh[2], bh[3], st + OB_HI + bByte);
        LDSM4(bh[4], bh[5], bh[6], bh[7], st + OB_HI + bByte + 16 * ROWB);
        #pragma unroll
        for (int t = 0; t < 4; ++t)
            LDSM4(ah[4*t], ah[4*t+1], ah[4*t+2], ah[4*t+3],
                  st + OA_HI + aByte + (uint32_t)t * 16 * ROWB);

        #pragma unroll
        for (int t = 0; t < 4; ++t)
            #pragma unroll
            for (int u = 0; u < 4; ++u) {
                const int p = u >> 1, q = u & 1;
                mma_f16(acc[t][u], &ah[4*t], bh[4*p + q], bh[4*p + q + 2]);
            }

        if (i + 4 < nk) issue(i + 4);   // issue-at-end (R5-proven placement)
    }

    // ---------------- epilogue (registers -> global, direct) ----------------
    const int l4  = lane >> 2;
    const int lc2 = (lane & 3) * 2;
    #pragma unroll
    for (int u = 0; u < 4; ++u) {
        const int col = bcol + wn * 32 + u * 8 + lc2;
        float b0 = 0.0f, b1 = 0.0f;
        if (BIAS) {
            b0 = __ldg(bias + col);
            b1 = __ldg(bias + col + 1);
        }
        #pragma unroll
        for (int t = 0; t < 4; ++t)
            #pragma unroll
            for (int h = 0; h < 2; ++h) {
                const int row = brow + wm * 64 + t * 16 + h * 8 + l4;
                // N even & col even -> pair [col, col+1] inside when col < N
                if (BOUND && (row >= M || col >= N)) continue;
                float v0 = acc[t][u][2*h + 0] * oscale;
                float v1 = acc[t][u][2*h + 1] * oscale;
                if (BIAS) { v0 += b0; v1 += b1; }
                if (RELU) { v0 = fmaxf(v0, 0.0f); v1 = fmaxf(v1, 0.0f); }
                const size_t o = (size_t)row * ldc + col;
                if (EMIT == 0) {
                    float2 f2; f2.x = v0; f2.y = v1;
                    *(float2*)(C + o) = f2;
                } else {
                    *(__half2*)(Ch + o) = __floats2half2_rn(v0, v1);
                }
            }
    }
}

// ---------------------------------------------------------------------------
// kernel_launch
// ---------------------------------------------------------------------------
extern "C" void kernel_launch(void* const* d_in, const int* in_sizes, int n_in,
                              void* d_out, int out_size)
{
    const float* x  = (const float*)d_in[0];   // [4096, 2048]
    const float* V1 = (const float*)d_in[1];   // [5794, 2897]
    const float* V2 = (const float*)d_in[2];   // [5794, 2897]
    float* out = (float*)d_out;                // [4096, 2048]

    __half *v1h, *v2h, *vh, *xh, *hh;
    float* gb;
    cudaGetSymbolAddress((void**)&v1h, g_V1hi);
    cudaGetSymbolAddress((void**)&v2h, g_V2hi);
    cudaGetSymbolAddress((void**)&vh,  g_Vh);
    cudaGetSymbolAddress((void**)&xh,  g_xh);
    cudaGetSymbolAddress((void**)&hh,  g_hh);
    cudaGetSymbolAddress((void**)&gb,  g_bias);

    auto k1 = gemm_mma<false, false, 1, true>;   // V  (fp16 out, bounded)
    auto k2 = gemm_mma<true,  true,  1, false>;  // h  (fp16 out)
    auto k3 = gemm_mma<true,  false, 0, false>;  // out (fp32)
    cudaFuncSetAttribute(k1, cudaFuncAttributeMaxDynamicSharedMemorySize, SMEM_1P);
    cudaFuncSetAttribute(k2, cudaFuncAttributeMaxDynamicSharedMemorySize, SMEM_1P);
    cudaFuncSetAttribute(k3, cudaFuncAttributeMaxDynamicSharedMemorySize, SMEM_1P);

    // 1. operand prep (vectorized, division-free)
    {
        pad_split_v<<<dim3(SZN_PAD, 2), 384>>>(V1, V2, v1h, v2h);
        int totx = BATCH * D_IN;                 // divisible by 8
        tohalf_vec<<<(totx / 8 + 255) / 256, 256>>>(x, xh, totx);
        bias_kernel<<<(D_FF + D_OUT) / 8, 256>>>(V1, V2, gb);
    }

    // 2. V = V1h @ V2h^T  (x4096 scaled) -> fp16 Vh (descale 2^-12)
    k1<<<dim3(SZN_PAD / 128, SZN_PAD / 128), 256, SMEM_1P>>>(
        (const u16*)v1h, (const u16*)v2h,
        nullptr, nullptr, vh,
        SZN, SZN, SZK_PAD, SZK_PAD, SZK_PAD, SZN, V_DESCALE);

    // 3. h = relu(xh @ W1h^T + b1) -> fp16
    k2<<<dim3(D_FF / 128, BATCH / 128), 256, SMEM_1P>>>(
        (const u16*)xh, (const u16*)vh,
        gb, nullptr, hh,
        BATCH, D_FF, D_IN, D_IN, D_IN, D_FF, 1.0f);

    // 4. out = hh @ W2h^T + b2 -> fp32
    k3<<<dim3(D_OUT / 128, BATCH / 128), 256, SMEM_1P>>>(
        (const u16*)hh, (const u16*)(vh + OFF_W2),
        gb + D_FF, out, nullptr,
        BATCH, D_OUT, D_FF, D_FF, D_FF, D_OUT, 1.0f);
}